// round 4
// baseline (speedup 1.0000x reference)
#include <cuda_runtime.h>
#include <math.h>
#include <float.h>

#define NW   1024
#define NOCT 12
#define NCOL 16
#define NB   8

// ---- static device scratch ----
__device__ float         g_hxn[NOCT * NW];
__device__ unsigned      g_nmin, g_nmax, g_omin, g_omax;
__device__ unsigned char g_idx[NW * NW];

__constant__ float c_pw[NOCT] = {
    1.0f, 1.5f, 2.25f, 3.375f, 5.0625f, 7.59375f, 11.390625f,
    17.0859375f, 25.62890625f, 38.443359375f, 57.6650390625f, 86.49755859375f
};

// ---- packed f32x2 helpers ----
__device__ __forceinline__ unsigned long long add2(unsigned long long a, unsigned long long b) {
    unsigned long long r; asm("add.rn.f32x2 %0, %1, %2;" : "=l"(r) : "l"(a), "l"(b)); return r;
}
__device__ __forceinline__ unsigned long long fmascale2(unsigned long long d, unsigned long long a, unsigned long long b) {
    asm("fma.rn.f32x2 %0, %0, %1, %2;" : "+l"(d) : "l"(a), "l"(b)); return d;
}
__device__ __forceinline__ unsigned long long pack2(float f) {
    unsigned long long r; asm("mov.b64 %0, {%1, %1};" : "=l"(r) : "f"(f)); return r;
}
__device__ __forceinline__ void unpack2(unsigned long long v, float& a, float& b) {
    asm("mov.b64 {%0, %1}, %2;" : "=f"(a), "=f"(b) : "l"(v));
}

// One block per octave; also inits the global min/max cells.
__global__ void k_octaves() {
    int i = threadIdx.x;
    int o = blockIdx.x;
    if (o == 0 && i == 0) {
        g_nmin = 0x7f7fffffu; g_nmax = 0u;
        g_omin = 0x7f7fffffu; g_omax = 0u;
    }
    __shared__ float smn[32], smx[32];

    float xi = __fmul_rn((float)i, 1.0f / 1023.0f);
    float scale = (float)((double)(320 << o) * 3.14159265358979323846);
    float arg = __fmul_rn(xi, scale);
    float s = (float)sin((double)arg);

    float mn = s, mx = s;
    #pragma unroll
    for (int off = 16; off; off >>= 1) {
        mn = fminf(mn, __shfl_xor_sync(0xffffffffu, mn, off));
        mx = fmaxf(mx, __shfl_xor_sync(0xffffffffu, mx, off));
    }
    if ((i & 31) == 0) { smn[i >> 5] = mn; smx[i >> 5] = mx; }
    __syncthreads();
    if (i < 32) {
        mn = smn[i]; mx = smx[i];
        #pragma unroll
        for (int off = 16; off; off >>= 1) {
            mn = fminf(mn, __shfl_xor_sync(0xffffffffu, mn, off));
            mx = fmaxf(mx, __shfl_xor_sync(0xffffffffu, mx, off));
        }
        if (i == 0) { smn[0] = mn; smx[0] = mx; }
    }
    __syncthreads();
    g_hxn[o * NW + i] = __fdiv_rn(__fsub_rn(s, smn[0]), __fsub_rn(smx[0], smn[0]));
}

// 4 pixels/thread -> global noise min/max
__global__ void k_nminmax() {
    int g = blockIdx.x * 256 + threadIdx.x;
    int i = g >> 8, j0 = (g & 255) << 2;
    float n0 = 0.f, n1 = 0.f, n2 = 0.f, n3 = 0.f;
    #pragma unroll
    for (int o = 0; o < NOCT; o++) {
        float a = __ldg(&g_hxn[o * NW + i]);
        float4 b = __ldg((const float4*)&g_hxn[o * NW + j0]);
        float p = c_pw[o];
        n0 = __fadd_rn(n0, __fmul_rn(__fadd_rn(a, b.x), p));
        n1 = __fadd_rn(n1, __fmul_rn(__fadd_rn(a, b.y), p));
        n2 = __fadd_rn(n2, __fmul_rn(__fadd_rn(a, b.z), p));
        n3 = __fadd_rn(n3, __fmul_rn(__fadd_rn(a, b.w), p));
    }
    float mn = fminf(fminf(n0, n1), fminf(n2, n3));
    float mx = fmaxf(fmaxf(n0, n1), fmaxf(n2, n3));
    #pragma unroll
    for (int off = 16; off; off >>= 1) {
        mn = fminf(mn, __shfl_xor_sync(0xffffffffu, mn, off));
        mx = fmaxf(mx, __shfl_xor_sync(0xffffffffu, mx, off));
    }
    __shared__ float smn[8], smx[8];
    int lane = threadIdx.x & 31, w = threadIdx.x >> 5;
    if (lane == 0) { smn[w] = mn; smx[w] = mx; }
    __syncthreads();
    if (threadIdx.x == 0) {
        mn = smn[0]; mx = smx[0];
        #pragma unroll
        for (int q = 1; q < 8; q++) { mn = fminf(mn, smn[q]); mx = fmaxf(mx, smx[q]); }
        atomicMin(&g_nmin, __float_as_uint(mn));
        atomicMax(&g_nmax, __float_as_uint(mx));
    }
}

// 4 pixels/thread: noise -> palette index, uchar4 stores
__global__ void k_makeidx() {
    int g = blockIdx.x * 256 + threadIdx.x;
    int i = g >> 8, j0 = (g & 255) << 2;
    float n0 = 0.f, n1 = 0.f, n2 = 0.f, n3 = 0.f;
    #pragma unroll
    for (int o = 0; o < NOCT; o++) {
        float a = __ldg(&g_hxn[o * NW + i]);
        float4 b = __ldg((const float4*)&g_hxn[o * NW + j0]);
        float p = c_pw[o];
        n0 = __fadd_rn(n0, __fmul_rn(__fadd_rn(a, b.x), p));
        n1 = __fadd_rn(n1, __fmul_rn(__fadd_rn(a, b.y), p));
        n2 = __fadd_rn(n2, __fmul_rn(__fadd_rn(a, b.z), p));
        n3 = __fadd_rn(n3, __fmul_rn(__fadd_rn(a, b.w), p));
    }
    float mn = __uint_as_float(g_nmin);
    float mx = __uint_as_float(g_nmax);
    float d = __fsub_rn(mx, mn);
    uchar4 v;
    v.x = (unsigned char)(int)rintf(__fmul_rn(__fdiv_rn(__fsub_rn(n0, mn), d), 15.0f));
    v.y = (unsigned char)(int)rintf(__fmul_rn(__fdiv_rn(__fsub_rn(n1, mn), d), 15.0f));
    v.z = (unsigned char)(int)rintf(__fmul_rn(__fdiv_rn(__fsub_rn(n2, mn), d), 15.0f));
    v.w = (unsigned char)(int)rintf(__fmul_rn(__fdiv_rn(__fsub_rn(n3, mn), d), 15.0f));
    ((uchar4*)g_idx)[g] = v;
}

// Separable box blur in color space. 8x32 tile, halo 12x36.
// MINMAX pass: global min/max reduction. WRITE pass: normalize + coalesced store.
template <bool WRITE>
__global__ void __launch_bounds__(256) k_blur(const float* __restrict__ colors,
                                              float* __restrict__ out) {
    __shared__ unsigned char tile[12][36];
    __shared__ unsigned long long colS[17][14];   // 24 floats per k, padded; k=16 is zeros
    __shared__ __align__(16) unsigned char sbuf[30720];   // union: vcs | stage
    __shared__ float smn[8], smx[8];

    typedef ulonglong2 (*vcs_t)[8][40];
    vcs_t vcs = (vcs_t)sbuf;                      // [6][8][40] ulonglong2
    float* stage = (float*)sbuf;                  // 8*8*96 floats = 24KB

    int tx = threadIdx.x, ty = threadIdx.y;
    int t = ty * 32 + tx;

    // palette -> smem, layout per k: f[q], q = b*3+c; k=16 and pads are zero
    for (int idx = t; idx < 17 * 28; idx += 256) {
        int k = idx / 28, q = idx % 28;
        float v = 0.0f;
        if (k < 16 && q < 24) v = colors[(q / 3) * 48 + k * 3 + (q % 3)];
        ((float*)&colS[k][0])[q] = v;
    }

    int bi0 = blockIdx.y * 8, bj0 = blockIdx.x * 32;
    for (int q = t; q < 12 * 36; q += 256) {
        int r = q / 36, cc = q % 36;
        int gi = bi0 + r - 2, gj = bj0 + cc - 2;
        unsigned char v = 16;  // zero-color sentinel (image border padding)
        if ((unsigned)gi < (unsigned)NW && (unsigned)gj < (unsigned)NW)
            v = g_idx[gi * NW + gj];
        tile[r][cc] = v;
    }
    __syncthreads();

    // Phase 2: vertical 5-tap color sums -> vcs[chunk][row][col]
    {
        int e = t;  // entries 0..255 by all, 256..287 by (t&7)==0 threads
        #pragma unroll 1
        for (int pass = 0; pass < 2; pass++) {
            if (pass == 1) {
                if ((t & 7) != 0) break;
                e = 256 + (t >> 3);
            }
            int r = e / 36, c = e % 36;
            unsigned long long a[12];
            #pragma unroll
            for (int m = 0; m < 12; m++) a[m] = 0ull;
            #pragma unroll
            for (int dy = 0; dy < 5; dy++) {
                int k = tile[r + dy][c];
                const ulonglong2* cp = (const ulonglong2*)&colS[k][0];
                #pragma unroll
                for (int m = 0; m < 6; m++) {
                    ulonglong2 v = cp[m];
                    a[2 * m]     = add2(a[2 * m],     v.x);
                    a[2 * m + 1] = add2(a[2 * m + 1], v.y);
                }
            }
            #pragma unroll
            for (int m = 0; m < 6; m++)
                vcs[m][r][c] = make_ulonglong2(a[2 * m], a[2 * m + 1]);
        }
    }
    __syncthreads();

    // Phase 3: horizontal 5-tap sum (conflict-free stride-16B reads)
    unsigned long long o[12];
    #pragma unroll
    for (int m = 0; m < 6; m++) {
        ulonglong2 v = vcs[m][ty][tx];
        o[2 * m] = v.x; o[2 * m + 1] = v.y;
    }
    #pragma unroll
    for (int dx = 1; dx < 5; dx++)
        #pragma unroll
        for (int m = 0; m < 6; m++) {
            ulonglong2 v = vcs[m][ty][tx + dx];
            o[2 * m]     = add2(o[2 * m],     v.x);
            o[2 * m + 1] = add2(o[2 * m + 1], v.y);
        }

    if (!WRITE) {
        float lmn = FLT_MAX, lmx = 0.0f;
        #pragma unroll
        for (int j = 0; j < 12; j++) {
            float a, b; unpack2(o[j], a, b);
            lmn = fminf(lmn, fminf(a, b));
            lmx = fmaxf(lmx, fmaxf(a, b));
        }
        lmn *= 0.04f; lmx *= 0.04f;
        #pragma unroll
        for (int off = 16; off; off >>= 1) {
            lmn = fminf(lmn, __shfl_xor_sync(0xffffffffu, lmn, off));
            lmx = fmaxf(lmx, __shfl_xor_sync(0xffffffffu, lmx, off));
        }
        int lane = t & 31, w = t >> 5;
        if (lane == 0) { smn[w] = lmn; smx[w] = lmx; }
        __syncthreads();
        if (t == 0) {
            lmn = smn[0]; lmx = smx[0];
            #pragma unroll
            for (int q = 1; q < 8; q++) { lmn = fminf(lmn, smn[q]); lmx = fmaxf(lmx, smx[q]); }
            atomicMin(&g_omin, __float_as_uint(lmn));
            atomicMax(&g_omax, __float_as_uint(lmx));
        }
    } else {
        float mn = __uint_as_float(g_omin);
        float mx = __uint_as_float(g_omax);
        float inv = 1.0f / (mx - mn);
        unsigned long long kwi2 = pack2(0.04f * inv);
        unsigned long long off2 = pack2(-mn * inv);

        __syncthreads();   // everyone done reading vcs before stage overwrites sbuf
        #pragma unroll
        for (int j = 0; j < 12; j++) {
            unsigned long long v = fmascale2(o[j], kwi2, off2);
            float a, b; unpack2(v, a, b);
            int q0 = 2 * j, q1 = 2 * j + 1;
            stage[((q0 / 3) * 8 + ty) * 96 + tx * 3 + (q0 % 3)] = a;
            stage[((q1 / 3) * 8 + ty) * 96 + tx * 3 + (q1 % 3)] = b;
        }
        __syncthreads();
        #pragma unroll
        for (int s = 0; s < 6; s++) {
            int m2 = t + 256 * s;          // 0..1535
            int b = m2 / 192;
            int rm = m2 % 192;
            int r = rm / 24, c4 = rm % 24;
            float4 v = *(const float4*)&stage[(b * 8 + r) * 96 + 4 * c4];
            long long base = (((long long)b * NW + (bi0 + r)) * NW + bj0) * 3 + 4 * c4;
            *(float4*)&out[base] = v;
        }
    }
}

extern "C" void kernel_launch(void* const* d_in, const int* in_sizes, int n_in,
                              void* d_out, int out_size) {
    (void)in_sizes; (void)n_in; (void)out_size;
    const float* colors = (const float*)d_in[0];
    float* out = (float*)d_out;

    k_octaves<<<NOCT, NW>>>();
    k_nminmax<<<(NW * NW / 4) / 256, 256>>>();
    k_makeidx<<<(NW * NW / 4) / 256, 256>>>();

    dim3 blk(32, 8);
    dim3 grd(NW / 32, NW / 8);
    k_blur<false><<<grd, blk>>>(colors, nullptr);
    k_blur<true><<<grd, blk>>>(colors, out);
}

// round 5
// speedup vs baseline: 1.2653x; 1.2653x over previous
#include <cuda_runtime.h>
#include <math.h>
#include <float.h>

#define NW   1024
#define NOCT 12
#define NCOL 16
#define NB   8

// ---- static device scratch ----
__device__ float         g_hxn[NOCT * NW];
__device__ unsigned      g_nmin, g_nmax, g_omin, g_omax;
__device__ unsigned char g_idx[NW * NW];

__constant__ float c_pw[NOCT] = {
    1.0f, 1.5f, 2.25f, 3.375f, 5.0625f, 7.59375f, 11.390625f,
    17.0859375f, 25.62890625f, 38.443359375f, 57.6650390625f, 86.49755859375f
};

// ---- packed f32x2 helpers ----
__device__ __forceinline__ void fma2(unsigned long long& d, unsigned long long a, unsigned long long b) {
    asm("fma.rn.f32x2 %0, %1, %2, %0;" : "+l"(d) : "l"(a), "l"(b));
}
__device__ __forceinline__ unsigned long long fmascale2(unsigned long long d, unsigned long long a, unsigned long long b) {
    asm("fma.rn.f32x2 %0, %0, %1, %2;" : "+l"(d) : "l"(a), "l"(b)); return d;
}
__device__ __forceinline__ unsigned long long pack2(float f) {
    unsigned long long r; asm("mov.b64 %0, {%1, %1};" : "=l"(r) : "f"(f)); return r;
}
__device__ __forceinline__ void unpack2(unsigned long long v, float& a, float& b) {
    asm("mov.b64 {%0, %1}, %2;" : "=f"(a), "=f"(b) : "l"(v));
}

// One block per octave; also inits the global min/max cells.
__global__ void k_octaves() {
    int i = threadIdx.x;
    int o = blockIdx.x;
    if (o == 0 && i == 0) {
        g_nmin = 0x7f7fffffu; g_nmax = 0u;
        g_omin = 0x7f7fffffu; g_omax = 0u;
    }
    __shared__ float smn[32], smx[32];

    float xi = __fmul_rn((float)i, 1.0f / 1023.0f);
    float scale = (float)((double)(320 << o) * 3.14159265358979323846);
    float arg = __fmul_rn(xi, scale);
    float s = (float)sin((double)arg);

    float mn = s, mx = s;
    #pragma unroll
    for (int off = 16; off; off >>= 1) {
        mn = fminf(mn, __shfl_xor_sync(0xffffffffu, mn, off));
        mx = fmaxf(mx, __shfl_xor_sync(0xffffffffu, mx, off));
    }
    if ((i & 31) == 0) { smn[i >> 5] = mn; smx[i >> 5] = mx; }
    __syncthreads();
    if (i < 32) {
        mn = smn[i]; mx = smx[i];
        #pragma unroll
        for (int off = 16; off; off >>= 1) {
            mn = fminf(mn, __shfl_xor_sync(0xffffffffu, mn, off));
            mx = fmaxf(mx, __shfl_xor_sync(0xffffffffu, mx, off));
        }
        if (i == 0) { smn[0] = mn; smx[0] = mx; }
    }
    __syncthreads();
    g_hxn[o * NW + i] = __fdiv_rn(__fsub_rn(s, smn[0]), __fsub_rn(smx[0], smn[0]));
}

// 4 pixels/thread -> global noise min/max
__global__ void k_nminmax() {
    int g = blockIdx.x * 256 + threadIdx.x;
    int i = g >> 8, j0 = (g & 255) << 2;
    float n0 = 0.f, n1 = 0.f, n2 = 0.f, n3 = 0.f;
    #pragma unroll
    for (int o = 0; o < NOCT; o++) {
        float a = __ldg(&g_hxn[o * NW + i]);
        float4 b = __ldg((const float4*)&g_hxn[o * NW + j0]);
        float p = c_pw[o];
        n0 = __fadd_rn(n0, __fmul_rn(__fadd_rn(a, b.x), p));
        n1 = __fadd_rn(n1, __fmul_rn(__fadd_rn(a, b.y), p));
        n2 = __fadd_rn(n2, __fmul_rn(__fadd_rn(a, b.z), p));
        n3 = __fadd_rn(n3, __fmul_rn(__fadd_rn(a, b.w), p));
    }
    float mn = fminf(fminf(n0, n1), fminf(n2, n3));
    float mx = fmaxf(fmaxf(n0, n1), fmaxf(n2, n3));
    #pragma unroll
    for (int off = 16; off; off >>= 1) {
        mn = fminf(mn, __shfl_xor_sync(0xffffffffu, mn, off));
        mx = fmaxf(mx, __shfl_xor_sync(0xffffffffu, mx, off));
    }
    __shared__ float smn[8], smx[8];
    int lane = threadIdx.x & 31, w = threadIdx.x >> 5;
    if (lane == 0) { smn[w] = mn; smx[w] = mx; }
    __syncthreads();
    if (threadIdx.x == 0) {
        mn = smn[0]; mx = smx[0];
        #pragma unroll
        for (int q = 1; q < 8; q++) { mn = fminf(mn, smn[q]); mx = fmaxf(mx, smx[q]); }
        atomicMin(&g_nmin, __float_as_uint(mn));
        atomicMax(&g_nmax, __float_as_uint(mx));
    }
}

// 4 pixels/thread: noise -> palette index, uchar4 stores
__global__ void k_makeidx() {
    int g = blockIdx.x * 256 + threadIdx.x;
    int i = g >> 8, j0 = (g & 255) << 2;
    float n0 = 0.f, n1 = 0.f, n2 = 0.f, n3 = 0.f;
    #pragma unroll
    for (int o = 0; o < NOCT; o++) {
        float a = __ldg(&g_hxn[o * NW + i]);
        float4 b = __ldg((const float4*)&g_hxn[o * NW + j0]);
        float p = c_pw[o];
        n0 = __fadd_rn(n0, __fmul_rn(__fadd_rn(a, b.x), p));
        n1 = __fadd_rn(n1, __fmul_rn(__fadd_rn(a, b.y), p));
        n2 = __fadd_rn(n2, __fmul_rn(__fadd_rn(a, b.z), p));
        n3 = __fadd_rn(n3, __fmul_rn(__fadd_rn(a, b.w), p));
    }
    float mn = __uint_as_float(g_nmin);
    float mx = __uint_as_float(g_nmax);
    float d = __fsub_rn(mx, mn);
    uchar4 v;
    v.x = (unsigned char)(int)rintf(__fmul_rn(__fdiv_rn(__fsub_rn(n0, mn), d), 15.0f));
    v.y = (unsigned char)(int)rintf(__fmul_rn(__fdiv_rn(__fsub_rn(n1, mn), d), 15.0f));
    v.z = (unsigned char)(int)rintf(__fmul_rn(__fdiv_rn(__fsub_rn(n2, mn), d), 15.0f));
    v.w = (unsigned char)(int)rintf(__fmul_rn(__fdiv_rn(__fsub_rn(n3, mn), d), 15.0f));
    ((uchar4*)g_idx)[g] = v;
}

// Separable box blur in COUNT space. 8x32 tile, halo 12x36.
// Vertical pass: packed 16-bin counts (u8 fields in 4 x u32) per column entry — pure ALU.
// Horizontal pass: conflict-free LDS.128 sums + one 16x24 palette dot with
// warp-uniform (broadcast) palette reads.
template <bool WRITE>
__global__ void __launch_bounds__(256) k_blur(const float* __restrict__ colors,
                                              float* __restrict__ out) {
    __shared__ unsigned char tile[12][36];
    __shared__ __align__(16) unsigned long long colS[NCOL][12];  // 24 floats per k
    __shared__ __align__(16) unsigned char sbuf[24576];          // union: vcnt | stage
    __shared__ float smn[8], smx[8];

    typedef uint4 (*vcnt_t)[40];
    vcnt_t vcnt = (vcnt_t)sbuf;                  // [8][40] uint4 (5120 B)
    float* stage = (float*)sbuf;                 // 8*8*96 floats = 24 KB (WRITE only)

    int tx = threadIdx.x, ty = threadIdx.y;      // blockDim = (32, 8)
    int t = ty * 32 + tx;

    // palette -> smem: colS[k] floats q = b*3+c
    for (int idx = t; idx < NCOL * 24; idx += 256) {
        int k = idx / 24, q = idx % 24;
        ((float*)&colS[k][0])[q] = colors[(q / 3) * 48 + k * 3 + (q % 3)];
    }

    int bi0 = blockIdx.y * 8, bj0 = blockIdx.x * 32;
    for (int q = t; q < 12 * 36; q += 256) {
        int r = q / 36, cc = q % 36;
        int gi = bi0 + r - 2, gj = bj0 + cc - 2;
        unsigned char v = 16;  // border sentinel: contributes no count
        if ((unsigned)gi < (unsigned)NW && (unsigned)gj < (unsigned)NW)
            v = g_idx[gi * NW + gj];
        tile[r][cc] = v;
    }
    __syncthreads();

    // Phase 2: vertical 5-tap packed counts (288 entries)
    for (int e = t; e < 8 * 36; e += 256) {
        int r = e / 36, c = e % 36;
        unsigned h0 = 0, h1 = 0, h2 = 0, h3 = 0;
        #pragma unroll
        for (int dy = 0; dy < 5; dy++) {
            int k = tile[r + dy][c];
            unsigned one = 1u << ((k & 3) * 8);
            unsigned w = (unsigned)k >> 2;
            h0 += (w == 0) ? one : 0u;
            h1 += (w == 1) ? one : 0u;
            h2 += (w == 2) ? one : 0u;
            h3 += (w == 3) ? one : 0u;
        }
        vcnt[r][c] = make_uint4(h0, h1, h2, h3);
    }
    __syncthreads();

    // Phase 3: horizontal 5-tap count sum (consecutive uint4 -> conflict-free)
    uint4 h = vcnt[ty][tx];
    #pragma unroll
    for (int dx = 1; dx < 5; dx++) {
        uint4 v = vcnt[ty][tx + dx];
        h.x += v.x; h.y += v.y; h.z += v.z; h.w += v.w;
    }

    // extract 16 counts -> packed f32x2 multipliers
    unsigned long long cnt2[NCOL];
    {
        unsigned hw[4] = {h.x, h.y, h.z, h.w};
        #pragma unroll
        for (int k = 0; k < NCOL; k++) {
            unsigned c = (hw[k >> 2] >> ((k & 3) * 8)) & 0xffu;
            cnt2[k] = pack2((float)c);
        }
    }

    // 16x24 dot: palette reads are warp-uniform broadcasts
    unsigned long long o[12];
    #pragma unroll
    for (int j = 0; j < 12; j++) o[j] = 0ull;
    #pragma unroll
    for (int k = 0; k < NCOL; k++) {
        const ulonglong2* cp = (const ulonglong2*)&colS[k][0];
        #pragma unroll
        for (int m = 0; m < 6; m++) {
            ulonglong2 v = cp[m];
            fma2(o[2 * m],     cnt2[k], v.x);
            fma2(o[2 * m + 1], cnt2[k], v.y);
        }
    }

    if (!WRITE) {
        float lmn = FLT_MAX, lmx = 0.0f;
        #pragma unroll
        for (int j = 0; j < 12; j++) {
            float a, b; unpack2(o[j], a, b);
            lmn = fminf(lmn, fminf(a, b));
            lmx = fmaxf(lmx, fmaxf(a, b));
        }
        lmn *= 0.04f; lmx *= 0.04f;
        #pragma unroll
        for (int off = 16; off; off >>= 1) {
            lmn = fminf(lmn, __shfl_xor_sync(0xffffffffu, lmn, off));
            lmx = fmaxf(lmx, __shfl_xor_sync(0xffffffffu, lmx, off));
        }
        int lane = t & 31, w = t >> 5;
        if (lane == 0) { smn[w] = lmn; smx[w] = lmx; }
        __syncthreads();
        if (t == 0) {
            lmn = smn[0]; lmx = smx[0];
            #pragma unroll
            for (int q = 1; q < 8; q++) { lmn = fminf(lmn, smn[q]); lmx = fmaxf(lmx, smx[q]); }
            atomicMin(&g_omin, __float_as_uint(lmn));
            atomicMax(&g_omax, __float_as_uint(lmx));
        }
    } else {
        float mn = __uint_as_float(g_omin);
        float mx = __uint_as_float(g_omax);
        float inv = 1.0f / (mx - mn);
        unsigned long long kwi2 = pack2(0.04f * inv);
        unsigned long long off2 = pack2(-mn * inv);

        __syncthreads();   // all phase-3 vcnt reads done before stage overwrites sbuf
        #pragma unroll
        for (int j = 0; j < 12; j++) {
            unsigned long long v = fmascale2(o[j], kwi2, off2);
            float a, b; unpack2(v, a, b);
            int q0 = 2 * j, q1 = 2 * j + 1;
            stage[((q0 / 3) * 8 + ty) * 96 + tx * 3 + (q0 % 3)] = a;
            stage[((q1 / 3) * 8 + ty) * 96 + tx * 3 + (q1 % 3)] = b;
        }
        __syncthreads();
        // 1536 float4 chunks per block, 6 per thread, fully coalesced STG.128
        #pragma unroll
        for (int s = 0; s < 6; s++) {
            int m2 = t + 256 * s;
            int b = m2 / 192;
            int rm = m2 % 192;
            int r = rm / 24, c4 = rm % 24;
            float4 v = *(const float4*)&stage[(b * 8 + r) * 96 + 4 * c4];
            long long base = (((long long)b * NW + (bi0 + r)) * NW + bj0) * 3 + 4 * c4;
            *(float4*)&out[base] = v;
        }
    }
}

extern "C" void kernel_launch(void* const* d_in, const int* in_sizes, int n_in,
                              void* d_out, int out_size) {
    (void)in_sizes; (void)n_in; (void)out_size;
    const float* colors = (const float*)d_in[0];
    float* out = (float*)d_out;

    k_octaves<<<NOCT, NW>>>();
    k_nminmax<<<(NW * NW / 4) / 256, 256>>>();
    k_makeidx<<<(NW * NW / 4) / 256, 256>>>();

    dim3 blk(32, 8);
    dim3 grd(NW / 32, NW / 8);
    k_blur<false><<<grd, blk>>>(colors, nullptr);
    k_blur<true><<<grd, blk>>>(colors, out);
}